// round 16
// baseline (speedup 1.0000x reference)
#include <cuda_runtime.h>
#include <cuda_bf16.h>

// Fixed shapes per reference setup_inputs
#define BB 8
#define CC 3
#define HH 224
#define WW 224
#define NPIX (HH * WW)          // 50176
#define NSEG 196
#define EE 768
#define NROWS (BB * NSEG)       // 1568
#define ACC_STRIDE 64           // 64 floats = 256 B per (rep,row); 6 used
#define NREP 4                  // accumulator replicas

#define SC_BLOCKS 392           // scatter role: (BB*NPIX/4)/256, 4 px/thread
#define PR_BLOCKS 392           // project role: 4 rows per block
#define NBLOCKS (SC_BLOCKS + PR_BLOCKS)   // 784: single co-resident wave
#define NTHREADS 256

#define WSM_FLOATS (5 * EE + EE)          // 4608 floats = 18432 B

// Scratch: 4 reps * 1568 rows * 256 B = 1.6 MB. Zero at module load; project
// blocks re-zero every word they consume -> zeroed for the next graph replay.
__device__ float g_acc[(long)NREP * NROWS * ACC_STRIDE];
// Monotone counters, never reset (deterministic per replay):
//   g_ctr  += SC_BLOCKS per launch (scatter arrivals, release semantics)
//   g_pctr += PR_BLOCKS per launch (project tickets -> launch index)
__device__ unsigned int g_ctr;
__device__ unsigned int g_pctr;

// ---------------------------------------------------------------------------
__device__ __forceinline__ void red_add_v4(float* addr, float a, float b,
                                           float c, float d) {
    asm volatile("red.global.add.v4.f32 [%0], {%1, %2, %3, %4};"
                 :: "l"(addr), "f"(a), "f"(b), "f"(c), "f"(d) : "memory");
}
__device__ __forceinline__ void red_add_v2(float* addr, float a, float b) {
    asm volatile("red.global.add.v2.f32 [%0], {%1, %2};"
                 :: "l"(addr), "f"(a), "f"(b) : "memory");
}
__device__ __forceinline__ float ld_cg(const float* p) {
    float v;
    asm volatile("ld.global.cg.f32 %0, [%1];" : "=f"(v) : "l"(p));
    return v;
}
__device__ __forceinline__ unsigned int ld_acquire_gpu(const unsigned int* p) {
    unsigned int v;
    asm volatile("ld.global.acquire.gpu.u32 %0, [%1];" : "=r"(v) : "l"(p));
    return v;
}
__device__ __forceinline__ void atom_add_release_gpu(unsigned int* p,
                                                     unsigned int v) {
    unsigned int old;
    asm volatile("atom.release.gpu.global.add.u32 %0, [%1], %2;"
                 : "=r"(old) : "l"(p), "r"(v) : "memory");
}

// ---------------------------------------------------------------------------
// One launch, two block roles, single co-resident wave.
// ---------------------------------------------------------------------------
__global__ void __launch_bounds__(NTHREADS, 8)
fused_roles_kernel(const float* __restrict__ img,
                   const int* __restrict__ seg,
                   const float* __restrict__ Wm,
                   const float* __restrict__ bias,
                   float* __restrict__ out) {
    __shared__ float wsm[WSM_FLOATS];      // W (5x768) then bias (768)
    __shared__ float raw[4][NREP][6];
    __shared__ float sums[4][6];

    const int tid = threadIdx.x;

    if (blockIdx.x < SC_BLOCKS) {
        // ================= SCATTER ROLE (proven shape) =================
        int t  = blockIdx.x * NTHREADS + tid;       // one 4-pixel group
        int b  = t / (NPIX / 4);
        int n4 = t - b * (NPIX / 4);
        int n  = n4 * 4;
        int h  = n / WW;
        int w  = n - h * WW;

        const float4 r4 = *reinterpret_cast<const float4*>(img + ((long)(b * CC + 0) * NPIX + n));
        const float4 g4 = *reinterpret_cast<const float4*>(img + ((long)(b * CC + 1) * NPIX + n));
        const float4 b4 = *reinterpret_cast<const float4*>(img + ((long)(b * CC + 2) * NPIX + n));
        const int4   s4 = *reinterpret_cast<const int4*>(seg + (long)b * NPIX + n);

        const float inv = 1.0f / 223.0f;
        float y = (float)h * inv;

        float rr[4] = {r4.x, r4.y, r4.z, r4.w};
        float gg[4] = {g4.x, g4.y, g4.z, g4.w};
        float bb[4] = {b4.x, b4.y, b4.z, b4.w};
        int   ss[4] = {s4.x, s4.y, s4.z, s4.w};

        float* rep = g_acc + (long)(blockIdx.x & (NREP - 1)) * ((long)NROWS * ACC_STRIDE);

#pragma unroll
        for (int i = 0; i < 4; i++) {
            float x = (float)(w + i) * inv;
            float* base = rep + (long)(b * NSEG + ss[i]) * ACC_STRIDE;
            red_add_v4(base, rr[i], gg[i], bb[i], x);
            red_add_v2(base + 4, y, 1.0f);
        }

        // Arrival: __syncthreads gives intra-block happens-before over all
        // threads' REDs; the release-atomic publishes them to the acquiring
        // project blocks. No per-thread MEMBAR.GPU needed.
        __syncthreads();
        if (tid == 0) atom_add_release_gpu(&g_ctr, 1u);
        return;
    }

    // ================= PROJECT ROLE (4 rows per block) =================
    const int pb   = blockIdx.x - SC_BLOCKS;   // 0..391
    const int row0 = pb * 4;

    // ---- Prefetch W + bias into smem WHILE scatter runs ----
    {
        float4* dst = reinterpret_cast<float4*>(wsm);
        const float4* srcW = reinterpret_cast<const float4*>(Wm);
        const float4* srcB = reinterpret_cast<const float4*>(bias);
#pragma unroll
        for (int k = 0; k < 5; k++) {          // 1152 float4 over 256 threads
            int i = tid + k * NTHREADS;
            if (i < 1152) dst[i] = (i < 960) ? srcW[i] : srcB[i - 960];
        }
    }

    // ---- Wait for all scatter arrivals of THIS launch ----
    if (tid == 0) {
        unsigned int ticket  = atomicAdd(&g_pctr, 1u);
        unsigned int launchi = ticket / (unsigned)PR_BLOCKS;
        unsigned int target  = (launchi + 1u) * (unsigned)SC_BLOCKS;
        while ((int)(ld_acquire_gpu(&g_ctr) - target) < 0) {
            __nanosleep(64);
        }
    }
    __syncthreads();   // publishes wsm and the acquired scatter results

    // ---- Acc read: 96 threads, one word each; reset own word ----
    if (tid < 96) {
        int row = tid / 24;
        int l   = tid - row * 24;
        int rep = l / 6;
        int j   = l - rep * 6;
        float* p = g_acc + (long)rep * ((long)NROWS * ACC_STRIDE)
                         + (long)(row0 + row) * ACC_STRIDE + j;
        float v = ld_cg(p);
        *p = 0.0f;                             // reset for next replay
        raw[row][rep][j] = v;
    }
    __syncthreads();

    if (tid < 24) {
        int row = tid / 6;
        int j   = tid - row * 6;
        sums[row][j] = raw[row][0][j] + raw[row][1][j]
                     + raw[row][2][j] + raw[row][3][j];
    }
    __syncthreads();

    // ---- FMA fan-out: 768 float4 slots over 256 threads (3 each) ----
    const float4* wsm4 = reinterpret_cast<const float4*>(wsm);
#pragma unroll
    for (int k = 0; k < 3; k++) {
        int slot = tid + k * NTHREADS;         // 0..767
        int row  = slot / 192;                 // 0..3
        int c4   = slot - row * 192;           // 0..191

        float cnt = sums[row][5];
        bool  empty = !(cnt > 0.0f);
        float invc  = empty ? 0.0f : (1.0f / cnt);
        float m0 = sums[row][0] * invc;
        float m1 = sums[row][1] * invc;
        float m2 = sums[row][2] * invc;
        float m3 = sums[row][3] * invc;
        float m4 = sums[row][4] * invc;

        float4 w0 = wsm4[0 * 192 + c4];
        float4 w1 = wsm4[1 * 192 + c4];
        float4 w2 = wsm4[2 * 192 + c4];
        float4 w3 = wsm4[3 * 192 + c4];
        float4 w4 = wsm4[4 * 192 + c4];
        float4 bv = wsm4[5 * 192 + c4];

        float4 r;
        r.x = m0 * w0.x + m1 * w1.x + m2 * w2.x + m3 * w3.x + m4 * w4.x + bv.x;
        r.y = m0 * w0.y + m1 * w1.y + m2 * w2.y + m3 * w3.y + m4 * w4.y + bv.y;
        r.z = m0 * w0.z + m1 * w1.z + m2 * w2.z + m3 * w3.z + m4 * w4.z + bv.z;
        r.w = m0 * w0.w + m1 * w1.w + m2 * w2.w + m3 * w3.w + m4 * w4.w + bv.w;
        if (empty) r = make_float4(0.f, 0.f, 0.f, 0.f);

        *reinterpret_cast<float4*>(out + (long)(row0 + row) * EE + c4 * 4) = r;
    }
}

// ---------------------------------------------------------------------------
extern "C" void kernel_launch(void* const* d_in, const int* in_sizes, int n_in,
                              void* d_out, int out_size) {
    const float* img  = (const float*)d_in[0];   // [8,3,224,224]
    const int*   seg  = (const int*)d_in[1];     // [8,224,224]
    const float* Wm   = (const float*)d_in[2];   // [5,768]
    const float* bias = (const float*)d_in[3];   // [768]
    float* out = (float*)d_out;                  // [8,196,768]

    (void)in_sizes; (void)n_in; (void)out_size;

    fused_roles_kernel<<<NBLOCKS, NTHREADS>>>(img, seg, Wm, bias, out);
}

// round 17
// speedup vs baseline: 1.3137x; 1.3137x over previous
#include <cuda_runtime.h>
#include <cuda_bf16.h>

// Fixed shapes per reference setup_inputs
#define BB 8
#define CC 3
#define HH 224
#define WW 224
#define NPIX (HH * WW)          // 50176
#define NSEG 196
#define EE 768
#define NROWS (BB * NSEG)       // 1568
#define ACC_STRIDE 64           // 64 floats = 256 B per (rep,row)
#define NREP 4                  // accumulator replicas

#define SC_BLOCKS 392           // scatter role: (BB*NPIX/4)/256, 4 px/thread
#define PR_BLOCKS 784           // project role: 2 rows per block
#define NBLOCKS (SC_BLOCKS + PR_BLOCKS)   // 1176 <= 1184 resident (8/SM)
#define NTHREADS 256

#define WSM_FLOATS (5 * EE + EE)          // 4608 floats = 18432 B

// Acc row layout (floats): [0]=r [1]=g [2]=b [3]=x (f32 RED sums),
// [4]=packed int (Sh*2048 + cnt, via red.add.u32), rest pad.
// Scratch zero at module load; project zeroes all consumed words each launch.
__device__ float g_acc[(long)NREP * NROWS * ACC_STRIDE];
// Monotone counters, never reset (deterministic per replay).
__device__ unsigned int g_ctr;
__device__ unsigned int g_pctr;

// ---------------------------------------------------------------------------
__device__ __forceinline__ void red_add_v4(float* addr, float a, float b,
                                           float c, float d) {
    asm volatile("red.global.add.v4.f32 [%0], {%1, %2, %3, %4};"
                 :: "l"(addr), "f"(a), "f"(b), "f"(c), "f"(d) : "memory");
}
__device__ __forceinline__ void red_add_u32(unsigned int* addr, unsigned int v) {
    asm volatile("red.global.add.u32 [%0], %1;" :: "l"(addr), "r"(v) : "memory");
}
__device__ __forceinline__ float ld_cg(const float* p) {
    float v;
    asm volatile("ld.global.cg.f32 %0, [%1];" : "=f"(v) : "l"(p));
    return v;
}
__device__ __forceinline__ unsigned int ld_acquire_gpu(const unsigned int* p) {
    unsigned int v;
    asm volatile("ld.global.acquire.gpu.u32 %0, [%1];" : "=r"(v) : "l"(p));
    return v;
}

// ---------------------------------------------------------------------------
// One launch, two block roles, single co-resident wave (R15 structure).
// ---------------------------------------------------------------------------
__global__ void __launch_bounds__(NTHREADS, 8)
fused_roles_kernel(const float* __restrict__ img,
                   const int* __restrict__ seg,
                   const float* __restrict__ Wm,
                   const float* __restrict__ bias,
                   float* __restrict__ out) {
    __shared__ float wsm[WSM_FLOATS];      // PR: W+bias; SC: reused as bins
    const int tid = threadIdx.x;

    if (blockIdx.x < SC_BLOCKS) {
        // ================= SCATTER ROLE =================
        // 1024 pixels per block, all within ONE batch (49 blocks per batch).
        int* bins = reinterpret_cast<int*>(wsm);    // 196 ints
        if (tid < NSEG) bins[tid] = 0;
        __syncthreads();

        int t  = blockIdx.x * NTHREADS + tid;       // one 4-pixel group
        int b  = t / (NPIX / 4);
        int n4 = t - b * (NPIX / 4);
        int n  = n4 * 4;
        int h  = n / WW;
        int w  = n - h * WW;

        const float4 r4 = *reinterpret_cast<const float4*>(img + ((long)(b * CC + 0) * NPIX + n));
        const float4 g4 = *reinterpret_cast<const float4*>(img + ((long)(b * CC + 1) * NPIX + n));
        const float4 b4 = *reinterpret_cast<const float4*>(img + ((long)(b * CC + 2) * NPIX + n));
        const int4   s4 = *reinterpret_cast<const int4*>(seg + (long)b * NPIX + n);

        const float inv = 1.0f / 223.0f;
        const int hpack = (h << 11) + 1;            // Sh*2048 + cnt payload

        float rr[4] = {r4.x, r4.y, r4.z, r4.w};
        float gg[4] = {g4.x, g4.y, g4.z, g4.w};
        float bb[4] = {b4.x, b4.y, b4.z, b4.w};
        int   ss[4] = {s4.x, s4.y, s4.z, s4.w};

        float* rep = g_acc + (long)(blockIdx.x & (NREP - 1)) * ((long)NROWS * ACC_STRIDE);

#pragma unroll
        for (int i = 0; i < 4; i++) {
            float x = (float)(w + i) * inv;
            float* base = rep + (long)(b * NSEG + ss[i]) * ACC_STRIDE;
            red_add_v4(base, rr[i], gg[i], bb[i], x);   // ONE global RED/pixel
            atomicAdd(&bins[ss[i]], hpack);             // smem histogram
        }
        __syncthreads();

        // Flush histogram: 196 near-coalesced u32 REDs into acc word 4.
        if (tid < NSEG) {
            unsigned int v = (unsigned int)bins[tid];
            if (v) {
                unsigned int* p = reinterpret_cast<unsigned int*>(
                    rep + (long)(b * NSEG + tid) * ACC_STRIDE + 4);
                red_add_u32(p, v);
            }
        }

        // Release: make REDs visible, arrive, exit (frees the SM slot).
        __threadfence();
        __syncthreads();
        if (tid == 0) atomicAdd(&g_ctr, 1u);
        return;
    }

    // ================= PROJECT ROLE (R15 shape: 2 rows/block) =================
    const int pb   = blockIdx.x - SC_BLOCKS;   // 0..783
    const int half = tid >> 7;                 // 0 or 1
    const int t128 = tid & 127;                // thread-in-half
    const int lane = tid & 31;
    const int s    = pb * 2 + half;            // row 0..1567

    // ---- Prefetch W + bias into smem WHILE scatter runs ----
    {
        float4* dst = reinterpret_cast<float4*>(wsm);
        const float4* srcW = reinterpret_cast<const float4*>(Wm);
        const float4* srcB = reinterpret_cast<const float4*>(bias);
#pragma unroll
        for (int k = 0; k < 5; k++) {          // 1152 float4 over 256 threads
            int i = tid + k * NTHREADS;
            if (i < 1152) dst[i] = (i < 960) ? srcW[i] : srcB[i - 960];
        }
    }

    // ---- Wait for all scatter arrivals of THIS launch ----
    if (tid == 0) {
        unsigned int ticket  = atomicAdd(&g_pctr, 1u);
        unsigned int launchi = ticket / (unsigned)PR_BLOCKS;
        unsigned int target  = (launchi + 1u) * (unsigned)SC_BLOCKS;
        while ((int)(ld_acquire_gpu(&g_ctr) - target) < 0) {
            __nanosleep(64);
        }
    }
    __syncthreads();   // publishes wsm and the acquired scatter results

    // ---- Acc read: lanes 0-19 (rep = lane/5, j = lane%5), shfl-reduce ----
    float v = 0.0f;
    if (lane < NREP * 5) {
        int rep = lane / 5;
        int j   = lane - rep * 5;
        v = ld_cg(g_acc + (long)rep * ((long)NROWS * ACC_STRIDE)
                        + (long)s * ACC_STRIDE + j);
    }
    int iv = __float_as_int(v);                // bit view for the int word

    float a0 = __shfl_sync(0xffffffffu, v, 0)  + __shfl_sync(0xffffffffu, v, 5)
             + __shfl_sync(0xffffffffu, v, 10) + __shfl_sync(0xffffffffu, v, 15);
    float a1 = __shfl_sync(0xffffffffu, v, 1)  + __shfl_sync(0xffffffffu, v, 6)
             + __shfl_sync(0xffffffffu, v, 11) + __shfl_sync(0xffffffffu, v, 16);
    float a2 = __shfl_sync(0xffffffffu, v, 2)  + __shfl_sync(0xffffffffu, v, 7)
             + __shfl_sync(0xffffffffu, v, 12) + __shfl_sync(0xffffffffu, v, 17);
    float a3 = __shfl_sync(0xffffffffu, v, 3)  + __shfl_sync(0xffffffffu, v, 8)
             + __shfl_sync(0xffffffffu, v, 13) + __shfl_sync(0xffffffffu, v, 18);
    int packed = __shfl_sync(0xffffffffu, iv, 4)  + __shfl_sync(0xffffffffu, iv, 9)
               + __shfl_sync(0xffffffffu, iv, 14) + __shfl_sync(0xffffffffu, iv, 19);

    int   cnt_i = packed & 2047;               // exact count
    int   sh    = packed >> 11;                // exact Σh
    bool  empty = (cnt_i == 0);
    float invc  = empty ? 0.0f : (1.0f / (float)cnt_i);
    const float inv223 = 1.0f / 223.0f;

    float m0 = a0 * invc;
    float m1 = a1 * invc;
    float m2 = a2 * invc;
    float m3 = a3 * invc;
    float m4 = ((float)sh * inv223) * invc;    // Σy / cnt, y = h/223

    // ---- FMA fan-out from smem W (conflict-free stride-1 LDS) ----
    float* orow = out + (long)s * EE;
#pragma unroll
    for (int k = 0; k < 6; k++) {              // 768 / 128 = 6 cols per thread
        int e = t128 + k * 128;
        float w = m0 * wsm[e]
                + m1 * wsm[EE + e]
                + m2 * wsm[2 * EE + e]
                + m3 * wsm[3 * EE + e]
                + m4 * wsm[4 * EE + e]
                + wsm[5 * EE + e];
        orow[e] = empty ? 0.0f : w;
    }

    // ---- Reset consumed acc words (offsets 0..7 cover words 0-4) ----
    __syncthreads();
    if (tid < 16) {                            // 2 rows * NREP * 2 float4
        int rrow = pb * 2 + (tid >> 3);
        int rep  = (tid >> 1) & 3;
        int h4   = tid & 1;
        reinterpret_cast<float4*>(g_acc + (long)rep * ((long)NROWS * ACC_STRIDE)
                                        + (long)rrow * ACC_STRIDE)[h4] =
            make_float4(0.f, 0.f, 0.f, 0.f);
    }
}

// ---------------------------------------------------------------------------
extern "C" void kernel_launch(void* const* d_in, const int* in_sizes, int n_in,
                              void* d_out, int out_size) {
    const float* img  = (const float*)d_in[0];   // [8,3,224,224]
    const int*   seg  = (const int*)d_in[1];     // [8,224,224]
    const float* Wm   = (const float*)d_in[2];   // [5,768]
    const float* bias = (const float*)d_in[3];   // [768]
    float* out = (float*)d_out;                  // [8,196,768]

    (void)in_sizes; (void)n_in; (void)out_size;

    fused_roles_kernel<<<NBLOCKS, NTHREADS>>>(img, seg, Wm, bias, out);
}